// round 16
// baseline (speedup 1.0000x reference)
#include <cuda_runtime.h>
#include <cuda_bf16.h>
#include <cuda_fp16.h>
#include <cstdint>

#define BATCH 64
#define TLEN 2048
#define JLEN 128
#define DDIM 512

#define TT   128              // t per CTA (N tile)
#define KC   32               // k per pipeline stage (half a 128B SW128 row)
#define NSTAGE (DDIM / KC)    // 16 stages
#define NTILE (TLEN / TT)     // 16 t-tiles

// smem offsets (bytes) within 64KB dynamic smem
#define A_HI 0
#define A_LO 16384
#define B_HI 32768
#define B_LO 49152
#define SM_TOTAL 65536

#define SWZ128(off) ((off) ^ (((off) >> 3) & 0x70))

// Scratch
__device__ __half g_p[(size_t)BATCH * JLEN * TLEN];            // exp(sim - m_local), fp16
__device__ float g_m[(size_t)BATCH * JLEN * NTILE];            // per-tile local max
__device__ float g_s[(size_t)BATCH * JLEN * NTILE];            // per-tile local expsum
__device__ float g_factor[(size_t)BATCH * JLEN * NTILE];       // exp(m-M)/S
__device__ __nv_bfloat16 g_qhi[(size_t)BATCH * JLEN * DDIM];   // (question*w) hi
__device__ __nv_bfloat16 g_qlo[(size_t)BATCH * JLEN * DDIM];   // (question*w) lo

// ---------------------------------------------------------------------------
// helpers
// ---------------------------------------------------------------------------
__device__ __forceinline__ uint32_t smem_u32(const void* p) {
    uint32_t a;
    asm("{ .reg .u64 t; cvta.to.shared.u64 t, %1; cvt.u32.u64 %0, t; }" : "=r"(a) : "l"(p));
    return a;
}

#define LDSM_X4(R, ADDR) \
    asm volatile("ldmatrix.sync.aligned.m8n8.x4.shared.b16 {%0,%1,%2,%3}, [%4];" \
        : "=r"((R)[0]), "=r"((R)[1]), "=r"((R)[2]), "=r"((R)[3]) : "r"(ADDR))

#define CP_ASYNC16(dst, src) \
    asm volatile("cp.async.cg.shared.global [%0], [%1], 16;" :: "r"(dst), "l"(src))
#define CP_COMMIT() asm volatile("cp.async.commit_group;" ::: "memory")
#define CP_WAIT0()  asm volatile("cp.async.wait_group 0;" ::: "memory")

__device__ __forceinline__ void mma16816(float* d, const uint32_t* a, const uint32_t* b) {
    asm volatile(
        "mma.sync.aligned.m16n8k16.row.col.f32.bf16.bf16.f32 "
        "{%0,%1,%2,%3}, {%4,%5,%6,%7}, {%8,%9}, {%0,%1,%2,%3};"
        : "+f"(d[0]), "+f"(d[1]), "+f"(d[2]), "+f"(d[3])
        : "r"(a[0]), "r"(a[1]), "r"(a[2]), "r"(a[3]), "r"(b[0]), "r"(b[1]));
}

// pack bf16(lo), bf16(hi) -> u32 {low16=bf16(lo), high16=bf16(hi)}  (round-nearest)
__device__ __forceinline__ uint32_t cvt2bf(float lo, float hi) {
    uint32_t r;
    asm("cvt.rn.bf16x2.f32 %0, %1, %2;" : "=r"(r) : "f"(hi), "f"(lo));
    return r;
}

// split float4 -> packed bf16 hi pair (h01,h23) and lo (residual) pair (l01,l23)
__device__ __forceinline__ void split4(const float4 v, uint32_t& h01, uint32_t& h23,
                                       uint32_t& l01, uint32_t& l23) {
    h01 = cvt2bf(v.x, v.y);
    h23 = cvt2bf(v.z, v.w);
    const float f0 = __uint_as_float(h01 << 16);
    const float f1 = __uint_as_float(h01 & 0xffff0000u);
    const float f2 = __uint_as_float(h23 << 16);
    const float f3 = __uint_as_float(h23 & 0xffff0000u);
    l01 = cvt2bf(v.x - f0, v.y - f1);
    l23 = cvt2bf(v.z - f2, v.w - f3);
}

// ---------------------------------------------------------------------------
// Kernel 0: split (question * w) into bf16 hi/lo global scratch
// ---------------------------------------------------------------------------
__global__ __launch_bounds__(128) void prep_kernel(
    const float* __restrict__ question,
    const float* __restrict__ weight)
{
    const int row = blockIdx.x;            // b*128 + j
    const int k4  = threadIdx.x * 4;
    const float4 q = __ldg(reinterpret_cast<const float4*>(question + (size_t)row * DDIM + k4));
    const float4 w = __ldg(reinterpret_cast<const float4*>(weight + k4));
    float4 v = make_float4(q.x * w.x, q.y * w.y, q.z * w.z, q.w * w.w);
    uint32_t h01, h23, l01, l23;
    split4(v, h01, h23, l01, l23);
    *reinterpret_cast<uint2*>(g_qhi + (size_t)row * DDIM + k4) = make_uint2(h01, h23);
    *reinterpret_cast<uint2*>(g_qlo + (size_t)row * DDIM + k4) = make_uint2(l01, l23);
}

// ---------------------------------------------------------------------------
// stage helpers for gemm pipeline (stage s covers k = [s*KC, s*KC+KC))
// ---------------------------------------------------------------------------
__device__ __forceinline__ void stage_a_cpasync(
    uint32_t sb, int b, int s, int qlr, int tid)
{
    const int kbase = (s & 1) << 6;      // 0 or 64 bytes
    const int kg    = s * KC;
    #pragma unroll
    for (int it = 0; it < 2; ++it) {
        const int idx = tid + it * 256;           // 0..511
        const int row = idx >> 2;                 // 0..127
        const int u   = idx & 3;                  // 16B unit
        if (row < qlr) {
            const size_t src = ((size_t)(b * JLEN + row)) * DDIM + kg + u * 8;
            const uint32_t off = SWZ128((uint32_t)(row * 128 + kbase + u * 16));
            CP_ASYNC16(sb + A_HI + off, g_qhi + src);
            CP_ASYNC16(sb + A_LO + off, g_qlo + src);
        }
    }
}

// ---------------------------------------------------------------------------
// Kernel 1: HMMA GEMM + fused softmax epilogue. No reg cap (avoid spills).
// 16-stage pipeline: stage s+1 staging overlaps stage s MMAs (half-row ping-pong).
// ---------------------------------------------------------------------------
__global__ __launch_bounds__(256) void gemm_kernel(
    const float* __restrict__ context,
    const int* __restrict__ qlen,
    const int* __restrict__ clen)
{
    extern __shared__ __align__(1024) char smem[];
    const int b  = blockIdx.y;
    const int t0 = blockIdx.x * TT;
    const int cl = clen[b];
    if (t0 >= cl) return;
    const int ql = qlen[b];
    const int qlr = (ql + 15) & ~15;

    const uint32_t sb = smem_u32(smem);
    const int tid  = threadIdx.x;
    const int lane = tid & 31;
    const int wid  = tid >> 5;

    const int jbase = (wid & 1) << 6;
    const int tbase = (wid >> 1) << 5;

    const int r    = lane & 7;
    const int quad = lane >> 3;

    float acc[4][4][4];
    #pragma unroll
    for (int mt = 0; mt < 4; ++mt)
        #pragma unroll
        for (int nt = 0; nt < 4; ++nt)
            #pragma unroll
            for (int i = 0; i < 4; ++i) acc[mt][nt][i] = 0.0f;

    // ---- prologue: stage 0 ----
    {
        stage_a_cpasync(sb, b, 0, qlr, tid);
        #pragma unroll
        for (int it = 0; it < 4; ++it) {
            const int idx = tid + it * 256;       // 0..1023
            const int row = idx >> 3;
            const int u   = idx & 7;
            const float4 c = __ldg(reinterpret_cast<const float4*>(
                context + ((size_t)(b * TLEN + t0 + row)) * DDIM + u * 4));
            uint32_t h01, h23, l01, l23;
            split4(c, h01, h23, l01, l23);
            const uint32_t off = SWZ128((uint32_t)(row * 128 + u * 8));
            *reinterpret_cast<uint2*>(smem + B_HI + off) = make_uint2(h01, h23);
            *reinterpret_cast<uint2*>(smem + B_LO + off) = make_uint2(l01, l23);
        }
        CP_COMMIT();
        CP_WAIT0();
        __syncthreads();
    }

    for (int s = 0; s < NSTAGE; ++s) {
        const int kbase = (s & 1) << 6;       // smem byte base of current stage
        const bool more = (s + 1 < NSTAGE);

        // ---- issue next-stage loads first (A cp.async + B LDG) ----
        float4 c0, c1, c2, c3;
        if (more) {
            stage_a_cpasync(sb, b, s + 1, qlr, tid);
            CP_COMMIT();
            const int kg = (s + 1) * KC;
            const float* cb = context + (size_t)(b * TLEN + t0) * DDIM + kg;
            const int row0 = tid >> 3, u = tid & 7;
            const int row1 = (tid + 256) >> 3;
            const int row2 = (tid + 512) >> 3;
            const int row3 = (tid + 768) >> 3;
            c0 = __ldg(reinterpret_cast<const float4*>(cb + (size_t)row0 * DDIM + u * 4));
            c1 = __ldg(reinterpret_cast<const float4*>(cb + (size_t)row1 * DDIM + u * 4));
            c2 = __ldg(reinterpret_cast<const float4*>(cb + (size_t)row2 * DDIM + u * 4));
            c3 = __ldg(reinterpret_cast<const float4*>(cb + (size_t)row3 * DDIM + u * 4));
        }

        // ---- MMAs for current stage (2 k16-steps) ----
        #pragma unroll
        for (int ks = 0; ks < 2; ++ks) {
            uint32_t bh[8], bl[8];
            #pragma unroll
            for (int p = 0; p < 2; ++p) {
                const int tile  = p * 2 + (quad >> 1);
                const int khalf = quad & 1;
                const int rowt  = tbase + tile * 8 + r;
                const uint32_t off = SWZ128((uint32_t)(rowt * 128 + kbase + ks * 32 + khalf * 16));
                LDSM_X4(bh + p * 4, sb + B_HI + off);
                LDSM_X4(bl + p * 4, sb + B_LO + off);
            }
            #pragma unroll
            for (int mt = 0; mt < 4; ++mt) {
                if (jbase + mt * 16 < ql) {
                    const int rowa = jbase + mt * 16 + ((quad & 1) << 3) + r;
                    const uint32_t off = SWZ128((uint32_t)(rowa * 128 + kbase + ks * 32 + ((quad >> 1) << 4)));
                    uint32_t ah[4], al[4];
                    LDSM_X4(ah, sb + A_HI + off);
                    LDSM_X4(al, sb + A_LO + off);
                    #pragma unroll
                    for (int nt = 0; nt < 4; ++nt) {
                        mma16816(acc[mt][nt], ah, bh + nt * 2);
                        mma16816(acc[mt][nt], al, bh + nt * 2);
                        mma16816(acc[mt][nt], ah, bl + nt * 2);
                    }
                }
            }
        }

        // ---- convert + store next-stage B into the other half-row ----
        if (more) {
            const uint32_t nkb = ((s + 1) & 1) << 6;
            uint32_t h01, h23, l01, l23;
            const int rows[4] = { tid >> 3, (tid + 256) >> 3, (tid + 512) >> 3, (tid + 768) >> 3 };
            const int u = tid & 7;
            split4(c0, h01, h23, l01, l23);
            uint32_t off = SWZ128((uint32_t)(rows[0] * 128 + nkb + u * 8));
            *reinterpret_cast<uint2*>(smem + B_HI + off) = make_uint2(h01, h23);
            *reinterpret_cast<uint2*>(smem + B_LO + off) = make_uint2(l01, l23);
            split4(c1, h01, h23, l01, l23);
            off = SWZ128((uint32_t)(rows[1] * 128 + nkb + u * 8));
            *reinterpret_cast<uint2*>(smem + B_HI + off) = make_uint2(h01, h23);
            *reinterpret_cast<uint2*>(smem + B_LO + off) = make_uint2(l01, l23);
            split4(c2, h01, h23, l01, l23);
            off = SWZ128((uint32_t)(rows[2] * 128 + nkb + u * 8));
            *reinterpret_cast<uint2*>(smem + B_HI + off) = make_uint2(h01, h23);
            *reinterpret_cast<uint2*>(smem + B_LO + off) = make_uint2(l01, l23);
            split4(c3, h01, h23, l01, l23);
            off = SWZ128((uint32_t)(rows[3] * 128 + nkb + u * 8));
            *reinterpret_cast<uint2*>(smem + B_HI + off) = make_uint2(h01, h23);
            *reinterpret_cast<uint2*>(smem + B_LO + off) = make_uint2(l01, l23);
            CP_WAIT0();
        }
        __syncthreads();
    }

    // =================== fused softmax epilogue ===================
    float* red  = reinterpret_cast<float*>(smem);          // 512 floats
    float* mfin = red + 512;                               // 128 floats

    const int g   = lane >> 2;
    const int tig = lane & 3;
    const int tw  = wid >> 1;
    const float NEG = -3.4028235e38f;

    float mrow[8];
    #pragma unroll
    for (int mt = 0; mt < 4; ++mt) {
        #pragma unroll
        for (int h = 0; h < 2; ++h) {
            float mm = NEG;
            #pragma unroll
            for (int nt = 0; nt < 4; ++nt) {
                const int tg = t0 + tbase + nt * 8 + tig * 2;
                const float v0 = (tg     < cl) ? acc[mt][nt][h * 2 + 0] : NEG;
                const float v1 = (tg + 1 < cl) ? acc[mt][nt][h * 2 + 1] : NEG;
                mm = fmaxf(mm, fmaxf(v0, v1));
            }
            mrow[mt * 2 + h] = mm;
        }
    }
    #pragma unroll
    for (int i = 0; i < 8; ++i) {
        mrow[i] = fmaxf(mrow[i], __shfl_xor_sync(0xffffffffu, mrow[i], 1));
        mrow[i] = fmaxf(mrow[i], __shfl_xor_sync(0xffffffffu, mrow[i], 2));
    }
    if (tig == 0) {
        #pragma unroll
        for (int mt = 0; mt < 4; ++mt)
            #pragma unroll
            for (int h = 0; h < 2; ++h) {
                const int row = jbase + mt * 16 + h * 8 + g;
                red[tw * 128 + row] = mrow[mt * 2 + h];
            }
    }
    __syncthreads();
    if (tid < 128)
        mfin[tid] = fmaxf(fmaxf(red[tid], red[128 + tid]),
                          fmaxf(red[256 + tid], red[384 + tid]));
    __syncthreads();

    float srow[8];
    #pragma unroll
    for (int mt = 0; mt < 4; ++mt) {
        const bool live = (jbase + mt * 16 < ql);
        #pragma unroll
        for (int h = 0; h < 2; ++h) {
            const int row = jbase + mt * 16 + h * 8 + g;
            float s = 0.0f;
            if (live) {
                const float mref = mfin[row];
                __half* prow = g_p + ((size_t)(b * JLEN + row)) * TLEN;
                #pragma unroll
                for (int nt = 0; nt < 4; ++nt) {
                    const int tg = t0 + tbase + nt * 8 + tig * 2;
                    const float e0 = (tg     < cl) ? __expf(acc[mt][nt][h * 2 + 0] - mref) : 0.0f;
                    const float e1 = (tg + 1 < cl) ? __expf(acc[mt][nt][h * 2 + 1] - mref) : 0.0f;
                    s += e0 + e1;
                    *reinterpret_cast<__half2*>(prow + tg) = __floats2half2_rn(e0, e1);
                }
            }
            srow[mt * 2 + h] = s;
        }
    }
    #pragma unroll
    for (int i = 0; i < 8; ++i) {
        srow[i] += __shfl_xor_sync(0xffffffffu, srow[i], 1);
        srow[i] += __shfl_xor_sync(0xffffffffu, srow[i], 2);
    }
    __syncthreads();
    if (tig == 0) {
        #pragma unroll
        for (int mt = 0; mt < 4; ++mt)
            #pragma unroll
            for (int h = 0; h < 2; ++h) {
                const int row = jbase + mt * 16 + h * 8 + g;
                red[tw * 128 + row] = srow[mt * 2 + h];
            }
    }
    __syncthreads();
    if (tid < 128) {
        const float S = red[tid] + red[128 + tid] + red[256 + tid] + red[384 + tid];
        const int tile = t0 >> 7;
        g_m[((size_t)(b * JLEN) + tid) * NTILE + tile] = mfin[tid];
        g_s[((size_t)(b * JLEN) + tid) * NTILE + tile] = S;
    }
}

// ---------------------------------------------------------------------------
// Kernel 2: combine tile stats -> factor[b][j][tile] = exp(m-M)/S_global
// ---------------------------------------------------------------------------
__global__ __launch_bounds__(256) void cstats_kernel(
    const int* __restrict__ qlen,
    const int* __restrict__ clen)
{
    const int idx = blockIdx.x * 256 + threadIdx.x;   // b*128+j
    const int b = idx >> 7;
    const int j = idx & 127;
    const int ql = qlen[b];
    const int cl = clen[b];
    const int ntl = (cl + TT - 1) / TT;

    float f[NTILE];
    if (j < ql) {
        float mv[NTILE];
        float M = -3.4028235e38f;
        for (int k = 0; k < ntl; ++k) {
            mv[k] = g_m[(size_t)idx * NTILE + k];
            M = fmaxf(M, mv[k]);
        }
        float S = 0.0f;
        for (int k = 0; k < ntl; ++k) {
            mv[k] = __expf(mv[k] - M);
            S += g_s[(size_t)idx * NTILE + k] * mv[k];
        }
        const float inv = 1.0f / S;
        #pragma unroll
        for (int k = 0; k < NTILE; ++k)
            f[k] = (k < ntl) ? mv[k] * inv : 0.0f;
    } else {
        #pragma unroll
        for (int k = 0; k < NTILE; ++k) f[k] = 0.0f;
    }

    float* dst = g_factor + (size_t)idx * NTILE;
    #pragma unroll
    for (int q = 0; q < 4; ++q)
        *reinterpret_cast<float4*>(dst + q * 4) =
            make_float4(f[q * 4 + 0], f[q * 4 + 1], f[q * 4 + 2], f[q * 4 + 3]);
}

// ---------------------------------------------------------------------------
// Kernel 3 (merged out): block = (tile, b). out[b][t] = sum_j p[j][t]*factor[j][tile]
// 8 warps x 16 j each; lane owns 4 t. smem reduction across warps.
// ---------------------------------------------------------------------------
__global__ __launch_bounds__(256) void out_kernel(
    const int* __restrict__ qlen,
    const int* __restrict__ clen,
    float* __restrict__ out)
{
    const int tile = blockIdx.x;
    const int b    = blockIdx.y;
    const int t0   = tile * TT;
    const int cl   = clen[b];
    const int tid  = threadIdx.x;

    if (t0 >= cl) {
        if (tid < TT) out[b * TLEN + t0 + tid] = 0.0f;
        return;
    }
    const int ql = qlen[b];

    __shared__ float sfac[JLEN];
    __shared__ float spart[8][TT];

    if (tid < JLEN)
        sfac[tid] = g_factor[((size_t)(b * JLEN + tid)) * NTILE + tile];
    __syncthreads();

    const int warp = tid >> 5;
    const int lane = tid & 31;

    float a0 = 0.f, a1 = 0.f, a2 = 0.f, a3 = 0.f;
    const __half* base = g_p + ((size_t)(b * JLEN)) * TLEN + t0 + lane * 4;
    #pragma unroll
    for (int jj = 0; jj < 16; ++jj) {
        const int j  = warp * 16 + jj;
        const int je = min(j, ql - 1);          // clamp: dead rows scaled by factor 0
        const uint2 u = *reinterpret_cast<const uint2*>(base + (size_t)je * TLEN);
        const float f = sfac[j];
        const float2 p0 = __half22float2(*reinterpret_cast<const __half2*>(&u.x));
        const float2 p1 = __half22float2(*reinterpret_cast<const __half2*>(&u.y));
        a0 += p0.x * f; a1 += p0.y * f; a2 += p1.x * f; a3 += p1.y * f;
    }
    spart[warp][lane * 4 + 0] = a0;
    spart[warp][lane * 4 + 1] = a1;
    spart[warp][lane * 4 + 2] = a2;
    spart[warp][lane * 4 + 3] = a3;
    __syncthreads();

    if (tid < TT) {
        float s = 0.f;
        #pragma unroll
        for (int w = 0; w < 8; ++w) s += spart[w][tid];
        out[b * TLEN + t0 + tid] = s;
    }
}

// ---------------------------------------------------------------------------
extern "C" void kernel_launch(void* const* d_in, const int* in_sizes, int n_in,
                              void* d_out, int out_size)
{
    const float* question = (const float*)d_in[0];
    const float* context  = (const float*)d_in[1];
    const int*   qlen     = (const int*)d_in[2];
    const int*   clen     = (const int*)d_in[3];
    const float* weight   = (const float*)d_in[4];
    float* out = (float*)d_out;

    cudaFuncSetAttribute(gemm_kernel, cudaFuncAttributeMaxDynamicSharedMemorySize, SM_TOTAL);

    prep_kernel<<<BATCH * JLEN, 128>>>(question, weight);

    dim3 g1(TLEN / TT, BATCH);              // 16 x 64
    gemm_kernel<<<g1, 256, SM_TOTAL>>>(context, qlen, clen);

    cstats_kernel<<<BATCH * JLEN / 256, 256>>>(qlen, clen);   // 32 x 256

    dim3 g3(NTILE, BATCH);                  // 16 x 64
    out_kernel<<<g3, 256>>>(qlen, clen, out);
}